// round 12
// baseline (speedup 1.0000x reference)
#include <cuda_runtime.h>

#define B_  4
#define SQ_ 512
#define SK_ 512
#define H_  256
#define A_  128

#define QT 8     // q rows per block
#define KT 32    // k tile

// scratch for projections (allocation-free rule: __device__ globals)
__device__ float g_Qt[B_ * SQ_ * A_];
__device__ float g_Kt[B_ * SK_ * A_];

__device__ __forceinline__ float fast_tanh(float x) {
    float y;
    asm("tanh.approx.f32 %0, %1;" : "=f"(y) : "f"(x));
    return y;
}

// ---------------------------------------------------------------------------
// Kernel 1: Qt = Q @ W_q, Kt = K @ W_k
// 8 rows per block, 128 threads (thread t owns output column a = t).
// ---------------------------------------------------------------------------
__global__ __launch_bounds__(128) void proj_kernel(
    const float* __restrict__ Q, const float* __restrict__ K,
    const float* __restrict__ Wq, const float* __restrict__ Wk)
{
    __shared__ float sX[QT][32];
    const int t = threadIdx.x;                 // 0..127 = output column a
    long rowBase = (long)blockIdx.x * QT;
    const float* X; const float* W; float* Out;
    const long nQ = (long)B_ * SQ_;
    if (rowBase < nQ) {
        X = Q + rowBase * H_;  W = Wq;  Out = g_Qt + rowBase * A_;
    } else {
        long r = rowBase - nQ;
        X = K + r * H_;        W = Wk;  Out = g_Kt + r * A_;
    }

    float acc[QT];
#pragma unroll
    for (int r = 0; r < QT; r++) acc[r] = 0.f;

    for (int h0 = 0; h0 < H_; h0 += 32) {
        // stage 8x32 input chunk (coalesced)
#pragma unroll
        for (int i = 0; i < 2; i++) {
            int idx = t + i * 128;
            int r = idx >> 5, hh = idx & 31;
            sX[r][hh] = X[(long)r * H_ + h0 + hh];
        }
        __syncthreads();
#pragma unroll
        for (int hh = 0; hh < 32; hh++) {
            float w = __ldg(&W[(long)(h0 + hh) * A_ + t]);
#pragma unroll
            for (int r = 0; r < QT; r++) acc[r] += sX[r][hh] * w;
        }
        __syncthreads();
    }
#pragma unroll
    for (int r = 0; r < QT; r++) Out[(long)r * A_ + t] = acc[r];
}

// ---------------------------------------------------------------------------
// Kernel 2 (fused): scores (tanh-additive) -> softmax -> weights @ V -> @ W_o + b_o
// One block = 8 q rows of one batch. 256 threads = 8 warps (warp w owns q row w).
// ---------------------------------------------------------------------------
__global__ __launch_bounds__(256) void attn_kernel(
    const float* __restrict__ Vv,   // (B, SK, H)
    const float* __restrict__ vvec, // (A)
    const float* __restrict__ Wo,   // (H, H)
    const float* __restrict__ bo,   // (H)
    float* __restrict__ out,        // (B, SQ, H)
    float* __restrict__ wout)       // (B, SQ, SK)
{
    __shared__ __align__(16) float sQt[QT][A_];      //  4 KB
    __shared__ __align__(16) float sv[A_];           // .5 KB
    __shared__            float sKtT[A_][KT + 1];    // 16.9 KB (padded, transposed)
    __shared__ __align__(16) float sW[QT][SK_];      // 16 KB  (scores -> weights)
    __shared__ __align__(16) float st[QT][H_];       //  8 KB  (weights @ V)

    const int tid = threadIdx.x;
    const int b  = blockIdx.x >> 6;          // 64 blocks per batch
    const int q0 = (blockIdx.x & 63) * QT;

    const float* Qt = g_Qt + (long)(b * SQ_ + q0) * A_;
    const float* Kt = g_Kt + (long)b * SK_ * A_;

    // stage Qt rows and v
    for (int i = tid; i < QT * A_; i += 256) sQt[i >> 7][i & 127] = Qt[i];
    if (tid < A_) sv[tid] = vvec[tid];
    __syncthreads();

    const int qw = tid >> 5;   // warp -> q row
    const int kk = tid & 31;   // lane -> k within tile

    // ---- Phase 1: scores --------------------------------------------------
    for (int k0 = 0; k0 < SK_; k0 += KT) {
        // load Kt tile transposed (coalesced gmem read, conflict-free smem store)
#pragma unroll
        for (int i = 0; i < (KT * A_) / 256; i++) {
            int idx = tid + i * 256;
            int kl = idx >> 7, a = idx & 127;
            sKtT[a][kl] = Kt[(long)(k0 + kl) * A_ + a];
        }
        __syncthreads();

        float acc = 0.f;
        const float4* q4 = (const float4*)sQt[qw];
        const float4* v4 = (const float4*)sv;
#pragma unroll 8
        for (int a4 = 0; a4 < A_ / 4; a4++) {
            float4 qv = q4[a4];
            float4 vv = v4[a4];
            int a = a4 * 4;
            acc += vv.x * fast_tanh(qv.x + sKtT[a + 0][kk]);
            acc += vv.y * fast_tanh(qv.y + sKtT[a + 1][kk]);
            acc += vv.z * fast_tanh(qv.z + sKtT[a + 2][kk]);
            acc += vv.w * fast_tanh(qv.w + sKtT[a + 3][kk]);
        }
        sW[qw][k0 + kk] = acc;
        __syncthreads();
    }

    // ---- Phase 2: softmax (one warp per q row, 512 values) ----------------
    {
        float vals[SK_ / 32];
        float m = -1e30f;
#pragma unroll
        for (int j = 0; j < SK_ / 32; j++) {
            vals[j] = sW[qw][kk + j * 32];
            m = fmaxf(m, vals[j]);
        }
#pragma unroll
        for (int o = 16; o; o >>= 1) m = fmaxf(m, __shfl_xor_sync(0xffffffffu, m, o));
        float s = 0.f;
#pragma unroll
        for (int j = 0; j < SK_ / 32; j++) {
            vals[j] = __expf(vals[j] - m);
            s += vals[j];
        }
#pragma unroll
        for (int o = 16; o; o >>= 1) s += __shfl_xor_sync(0xffffffffu, s, o);
        float inv = 1.f / s;
        float* wrow = wout + (long)(b * SQ_ + q0 + qw) * SK_;
#pragma unroll
        for (int j = 0; j < SK_ / 32; j++) {
            float w = vals[j] * inv;
            sW[qw][kk + j * 32] = w;
            wrow[kk + j * 32] = w;      // coalesced weights output
        }
    }
    __syncthreads();

    // ---- Phase 3: t = weights @ V  (thread owns h = tid) ------------------
    {
        const int h = tid;
        float acc[QT];
#pragma unroll
        for (int q = 0; q < QT; q++) acc[q] = 0.f;
        const float* Vb = Vv + (long)b * SK_ * H_;
        for (int k = 0; k < SK_; k += 4) {
            float v0 = __ldg(&Vb[(long)(k + 0) * H_ + h]);
            float v1 = __ldg(&Vb[(long)(k + 1) * H_ + h]);
            float v2 = __ldg(&Vb[(long)(k + 2) * H_ + h]);
            float v3 = __ldg(&Vb[(long)(k + 3) * H_ + h]);
#pragma unroll
            for (int q = 0; q < QT; q++) {
                float4 w4 = *(const float4*)&sW[q][k];   // broadcast LDS.128
                acc[q] += w4.x * v0 + w4.y * v1 + w4.z * v2 + w4.w * v3;
            }
        }
#pragma unroll
        for (int q = 0; q < QT; q++) st[q][h] = acc[q];
    }
    __syncthreads();

    // ---- Phase 4: out = t @ W_o + b_o  (thread owns h2 = tid) -------------
    {
        const int h2 = tid;
        float bias = bo[h2];
        float acc[QT];
#pragma unroll
        for (int q = 0; q < QT; q++) acc[q] = bias;
        for (int h = 0; h < H_; h += 4) {
            float w0 = __ldg(&Wo[(long)(h + 0) * H_ + h2]);
            float w1 = __ldg(&Wo[(long)(h + 1) * H_ + h2]);
            float w2 = __ldg(&Wo[(long)(h + 2) * H_ + h2]);
            float w3 = __ldg(&Wo[(long)(h + 3) * H_ + h2]);
#pragma unroll
            for (int q = 0; q < QT; q++) {
                float4 t4 = *(const float4*)&st[q][h];   // broadcast LDS.128
                acc[q] += t4.x * w0 + t4.y * w1 + t4.z * w2 + t4.w * w3;
            }
        }
        float* orow = out + (long)(b * SQ_ + q0) * H_;
#pragma unroll
        for (int q = 0; q < QT; q++) orow[(long)q * H_ + h2] = acc[q];
    }
}

// ---------------------------------------------------------------------------
// Inputs (metadata order): Q, K, V, W_q, W_k, v, W_o, b_o
// Output: [out (B*SQ*H) | weights (B*SQ*SK)]
// ---------------------------------------------------------------------------
extern "C" void kernel_launch(void* const* d_in, const int* in_sizes, int n_in,
                              void* d_out, int out_size)
{
    (void)in_sizes; (void)n_in; (void)out_size;
    const float* Q  = (const float*)d_in[0];
    const float* K  = (const float*)d_in[1];
    const float* V  = (const float*)d_in[2];
    const float* Wq = (const float*)d_in[3];
    const float* Wk = (const float*)d_in[4];
    const float* v  = (const float*)d_in[5];
    const float* Wo = (const float*)d_in[6];
    const float* bo = (const float*)d_in[7];

    float* out  = (float*)d_out;
    float* wout = out + (long)B_ * SQ_ * H_;

    // Qt and Kt projections: (B*SQ + B*SK) rows / 8 rows per block = 512 blocks
    proj_kernel<<<(B_ * SQ_ + B_ * SK_) / QT, 128>>>(Q, K, Wq, Wk);

    // fused scores + softmax + PV + output projection
    attn_kernel<<<B_ * (SQ_ / QT), 256>>>(V, v, Wo, bo, out, wout);
}